// round 7
// baseline (speedup 1.0000x reference)
#include <cuda_runtime.h>

#define H 512
#define W 512
#define NPTS 12
#define NMAPS 16          // B(8) * 2 groups
#define TSAT 21.0f        // d >= TSAT -> tanh(2*sqrt(d)) == 1.0f exactly in fp32
#define ROWS_PER_BLK 16
#define NBLK (NMAPS * H / ROWS_PER_BLK)   // 512 blocks -> single wave

typedef unsigned long long ull;

// ---- packed fp32 helpers ----
__device__ __forceinline__ ull f32x2_add(ull a, ull b) {
    ull r; asm("add.rn.f32x2 %0, %1, %2;" : "=l"(r) : "l"(a), "l"(b)); return r;
}
__device__ __forceinline__ ull f32x2_fma(ull a, ull b, ull c) {
    ull r; asm("fma.rn.f32x2 %0, %1, %2, %3;" : "=l"(r) : "l"(a), "l"(b), "l"(c)); return r;
}
__device__ __forceinline__ ull pack2(float lo, float hi) {
    ull r; asm("mov.b64 %0, {%1, %2};" : "=l"(r) : "f"(lo), "f"(hi)); return r;
}
__device__ __forceinline__ void unpack2(ull v, float& lo, float& hi) {
    asm("mov.b64 {%0, %1}, %2;" : "=f"(lo), "=f"(hi) : "l"(v));
}

// tanh(2*sqrt(d)) = 1 - 2/(exp(4*sqrt(d)) + 1); only called with d < TSAT.
__device__ __forceinline__ float fast_out(float d) {
    float s, t, r;
    asm("sqrt.approx.f32 %0, %1;" : "=f"(s) : "f"(d));
    float e = 5.770780163555852f * s;          // 4*log2(e)*sqrt(d)
    asm("ex2.approx.f32 %0, %1;" : "=f"(t) : "f"(e));
    float tp1 = t + 1.0f;
    asm("rcp.approx.f32 %0, %1;" : "=f"(r) : "f"(tp1));
    return fmaf(-2.0f, r, 1.0f);
}

// One block = (map, 16-row band). 256 threads. Single-wave grid (512 blocks).
__global__ __launch_bounds__(256) void distmaps_kernel(
    const float* __restrict__ coords,   // (8, 24, 3)
    float* __restrict__ out)            // (8, 2, 512, 512)
{
    const int m   = blockIdx.x >> 5;              // map 0..15
    const int r0  = (blockIdx.x & 31) * ROWS_PER_BLK;
    const int tid = threadIdx.x;

    __shared__ float sp_y[NPTS];
    __shared__ float sp_x[NPTS];
    __shared__ int   sp_v[NPTS];                  // valid flag
    __shared__ int   s_cnt[ROWS_PER_BLK];
    __shared__ float s_nx[ROWS_PER_BLK][NPTS];    // -x * 0.2
    __shared__ float s_a [ROWS_PER_BLK][NPTS];    // row term ((r-y)*0.2)^2
    __shared__ int   s_fb[ROWS_PER_BLK][NPTS];    // first float4 column of window

    if (tid < NPTS) {
        const float* q = coords + (m * NPTS + tid) * 3;
        float y = q[0];
        float x = q[1];
        sp_y[tid] = y;
        sp_x[tid] = x;
        sp_v[tid] = (fmaxf(y, x) >= 0.0f) ? 1 : 0;
    }
    if (tid < ROWS_PER_BLK) s_cnt[tid] = 0;
    __syncthreads();

    // Build per-row active point lists: 16 rows x 12 points = 192 tests.
    if (tid < ROWS_PER_BLK * NPTS) {
        const int j  = tid >> 4;      // point 0..11
        const int ri = tid & 15;      // row-in-band 0..15
        if (sp_v[j]) {
            float y = sp_y[j];
            float t = ((float)(r0 + ri) - y) * 0.2f;
            float a = t * t;
            if (a < TSAT) {
                int pos = atomicAdd(&s_cnt[ri], 1);
                float x = sp_x[j];
                s_nx[ri][pos] = -x * 0.2f;
                s_a [ri][pos] = a;
                s_fb[ri][pos] = (((int)floorf(x) - 23) & ~3) >> 2;
            }
        }
    }
    __syncthreads();

    const int c4   = tid & 127;                   // float4 column 0..127
    const int rhal = tid >> 7;                    // 0 or 1

    // 8 iterations x 2 rows = 16 rows. 128 threads per row, 1 float4 each.
#pragma unroll
    for (int it = 0; it < 8; it++) {
        const int ri = it * 2 + rhal;
        const int r  = r0 + ri;
        const int cnt = s_cnt[ri];

        bool covered = false;
        for (int e = 0; e < cnt; e++)
            covered |= (unsigned)(c4 - s_fb[ri][e]) <= 12u;

        float4 v = make_float4(1.0f, 1.0f, 1.0f, 1.0f);
        if (covered) {
            const int c = c4 * 4;
            ull cs0 = pack2((float)c * 0.2f,       (float)(c + 1) * 0.2f);
            ull cs1 = pack2((float)(c + 2) * 0.2f, (float)(c + 3) * 0.2f);
            float m0 = 1.0e6f, m1 = 1.0e6f, m2 = 1.0e6f, m3 = 1.0e6f;
            for (int e = 0; e < cnt; e++) {
                float nx = s_nx[ri][e];
                float a  = s_a [ri][e];
                ull nxv = pack2(nx, nx);
                ull av  = pack2(a, a);
                ull dc, d;
                float d0, d1;
                dc = f32x2_add(cs0, nxv); d = f32x2_fma(dc, dc, av);
                unpack2(d, d0, d1); m0 = fminf(m0, d0); m1 = fminf(m1, d1);
                dc = f32x2_add(cs1, nxv); d = f32x2_fma(dc, dc, av);
                unpack2(d, d0, d1); m2 = fminf(m2, d0); m3 = fminf(m3, d1);
            }
            v.x = (m0 < TSAT) ? fast_out(m0) : 1.0f;
            v.y = (m1 < TSAT) ? fast_out(m1) : 1.0f;
            v.z = (m2 < TSAT) ? fast_out(m2) : 1.0f;
            v.w = (m3 < TSAT) ? fast_out(m3) : 1.0f;
        }

        ((float4*)(out + ((size_t)m * H + r) * W))[c4] = v;
    }
}

extern "C" void kernel_launch(void* const* d_in, const int* in_sizes, int n_in,
                              void* d_out, int out_size)
{
    const float* coords = nullptr;
    for (int i = 0; i < n_in; i++) {
        if (in_sizes[i] == 8 * 24 * 3) { coords = (const float*)d_in[i]; break; }
    }
    if (!coords) coords = (const float*)d_in[n_in - 1];

    float* out = (float*)d_out;

    distmaps_kernel<<<NBLK, 256>>>(coords, out);
}

// round 8
// speedup vs baseline: 1.4060x; 1.4060x over previous
#include <cuda_runtime.h>

#define H 512
#define W 512
#define NPTS 12
#define NMAPS 16          // B(8) * 2 groups
#define TSAT 21.0f        // d >= TSAT -> tanh(2*sqrt(d)) == 1.0f exactly in fp32

typedef unsigned long long ull;

// ---- packed fp32 helpers ----
__device__ __forceinline__ ull f32x2_add(ull a, ull b) {
    ull r; asm("add.rn.f32x2 %0, %1, %2;" : "=l"(r) : "l"(a), "l"(b)); return r;
}
__device__ __forceinline__ ull f32x2_fma(ull a, ull b, ull c) {
    ull r; asm("fma.rn.f32x2 %0, %1, %2, %3;" : "=l"(r) : "l"(a), "l"(b), "l"(c)); return r;
}
__device__ __forceinline__ ull pack2(float lo, float hi) {
    ull r; asm("mov.b64 %0, {%1, %2};" : "=l"(r) : "f"(lo), "f"(hi)); return r;
}
__device__ __forceinline__ void unpack2(ull v, float& lo, float& hi) {
    asm("mov.b64 {%0, %1}, %2;" : "=f"(lo), "=f"(hi) : "l"(v));
}

// tanh(2*sqrt(d)) = 1 - 2/(exp(4*sqrt(d)) + 1); only called with d < TSAT.
__device__ __forceinline__ float fast_out(float d) {
    float s, t, r;
    asm("sqrt.approx.f32 %0, %1;" : "=f"(s) : "f"(d));
    float e = 5.770780163555852f * s;          // 4*log2(e)*sqrt(d)
    asm("ex2.approx.f32 %0, %1;" : "=f"(t) : "f"(e));
    float tp1 = t + 1.0f;
    asm("rcp.approx.f32 %0, %1;" : "=f"(r) : "f"(tp1));
    return fmaf(-2.0f, r, 1.0f);
}

// Block = (map, 2 rows), 256 threads. Grid = 16 * 256 = 4096 blocks.
// 24 threads build per-row 128-bit coverage masks + compacted point lists;
// each thread then tests ONE bit: clear -> store 1.0f (5 instrs),
// set (~13%) -> full min + tanh over the (tiny) active list.
__global__ __launch_bounds__(256) void distmaps_kernel(
    const float* __restrict__ coords,   // (8, 24, 3)
    float* __restrict__ out)            // (8, 2, 512, 512)
{
    const int b   = blockIdx.x;
    const int m   = b >> 8;             // map 0..15
    const int r0  = (b & 255) * 2;      // first row of the pair
    const int tid = threadIdx.x;

    __shared__ ull   s_mask[2][2];      // 128-bit coverage mask per row
    __shared__ int   s_cnt[2];
    __shared__ float s_nx[2][NPTS];     // -x * 0.2
    __shared__ float s_a [2][NPTS];     // row term ((r-y)*0.2)^2

    if (tid < 4) ((ull*)s_mask)[tid] = 0ull;
    if (tid < 2) s_cnt[tid] = 0;
    __syncthreads();

    if (tid < 2 * NPTS) {
        const int ri = (tid >= NPTS) ? 1 : 0;
        const int j  = tid - ri * NPTS;
        const float* q = coords + (m * NPTS + j) * 3;
        float y = q[0];
        float x = q[1];
        if (fmaxf(y, x) >= 0.0f) {
            float t = ((float)(r0 + ri) - y) * 0.2f;
            float a = t * t;
            if (a < TSAT) {
                int pos = atomicAdd(&s_cnt[ri], 1);
                s_nx[ri][pos] = -x * 0.2f;
                s_a [ri][pos] = a;
                int fb = (((int)floorf(x) - 23) & ~3) >> 2;   // first float4 col
                int lo = max(fb, 0);
                int hi = min(fb + 12, 127);
#pragma unroll
                for (int w = 0; w < 2; w++) {
                    int l = lo - 64 * w, h = hi - 64 * w;
                    if (h >= 0 && l <= 63) {
                        l = max(l, 0); h = min(h, 63);
                        ull bits = ((1ull << (h - l + 1)) - 1ull) << l;
                        atomicOr(&s_mask[ri][w], bits);
                    }
                }
            }
        }
    }
    __syncthreads();

    const int ri = tid >> 7;            // row half 0/1
    const int c4 = tid & 127;           // float4 column
    const int r  = r0 + ri;

    float4 v = make_float4(1.0f, 1.0f, 1.0f, 1.0f);
    const bool covered = (s_mask[ri][c4 >> 6] >> (c4 & 63)) & 1ull;

    if (covered) {
        const int c = c4 * 4;
        ull cs0 = pack2((float)c * 0.2f,       (float)(c + 1) * 0.2f);
        ull cs1 = pack2((float)(c + 2) * 0.2f, (float)(c + 3) * 0.2f);
        float m0 = 1.0e6f, m1 = 1.0e6f, m2 = 1.0e6f, m3 = 1.0e6f;
        const int cnt = s_cnt[ri];
        for (int e = 0; e < cnt; e++) {
            float nx = s_nx[ri][e];
            float a  = s_a [ri][e];
            ull nxv = pack2(nx, nx);
            ull av  = pack2(a, a);
            ull dc, d;
            float d0, d1;
            dc = f32x2_add(cs0, nxv); d = f32x2_fma(dc, dc, av);
            unpack2(d, d0, d1); m0 = fminf(m0, d0); m1 = fminf(m1, d1);
            dc = f32x2_add(cs1, nxv); d = f32x2_fma(dc, dc, av);
            unpack2(d, d0, d1); m2 = fminf(m2, d0); m3 = fminf(m3, d1);
        }
        v.x = (m0 < TSAT) ? fast_out(m0) : 1.0f;
        v.y = (m1 < TSAT) ? fast_out(m1) : 1.0f;
        v.z = (m2 < TSAT) ? fast_out(m2) : 1.0f;
        v.w = (m3 < TSAT) ? fast_out(m3) : 1.0f;
    }

    ((float4*)(out + ((size_t)m * H + r) * W))[c4] = v;
}

extern "C" void kernel_launch(void* const* d_in, const int* in_sizes, int n_in,
                              void* d_out, int out_size)
{
    const float* coords = nullptr;
    for (int i = 0; i < n_in; i++) {
        if (in_sizes[i] == 8 * 24 * 3) { coords = (const float*)d_in[i]; break; }
    }
    if (!coords) coords = (const float*)d_in[n_in - 1];

    float* out = (float*)d_out;

    distmaps_kernel<<<NMAPS * 256, 256>>>(coords, out);
}